// round 16
// baseline (speedup 1.0000x reference)
#include <cuda_runtime.h>
#include <math_constants.h>

// x [B=64, C=512, H=28, W=28] fp32; cc [B,28,28] bool widened to int32.
// out [B, 2C]: out[b,c]   = (sum_hw x[b,c,hw]*cc[b,hw] + x[b,c,0]) / max(cnt_b,1)
//              out[b,C+c] = max_hw x[b,c,hw]
//
// R8 skeleton (verified fastest ~18.9us) with 128-thread CTAs: identical
// per-warp instruction stream (7 front-batched float4 LDGs, int4 mask loads,
// warp reduce, no smem/barriers), but finer CTA granularity -> smoother
// last-wave tail and less bursty per-SM load injection. Grid 8192 x 128.

#define HW   784
#define C_DIM 512
#define THREADS 128
#define ROWS_PER_CTA 4

__global__ __launch_bounds__(THREADS) void pool_kernel(
    const float* __restrict__ x,
    const int* __restrict__ cc,
    float* __restrict__ out)
{
    const int tid  = threadIdx.x;
    const int wid  = tid >> 5;
    const int lane = tid & 31;

    const int bc = blockIdx.x * ROWS_PER_CTA + wid;   // this warp's row
    const int b  = bc >> 9;

    const float4* __restrict__ xr = reinterpret_cast<const float4*>(x + (size_t)bc * HW);
    const int4*   __restrict__ mr = reinterpret_cast<const int4*>(cc + (size_t)b * HW);

    // ---- 1. Front-batch all x loads (196 = 6*32 + 4) ----
    float4 v[7];
    #pragma unroll
    for (int j = 0; j < 6; j++) v[j] = xr[lane + 32 * j];
    const bool tail = (lane < 4);
    if (tail) v[6] = xr[lane + 192];

    // ---- 2. Consume with per-warp mask loads (L1 hits, overlap x latency) ----
    float sum0 = 0.0f, sum1 = 0.0f;
    int   icnt = 0;
    float mx   = -CUDART_INF_F;

    #pragma unroll
    for (int j = 0; j < 6; j++) {
        int4 m = mr[lane + 32 * j];
        sum0 += (m.x ? v[j].x : 0.0f) + (m.y ? v[j].y : 0.0f);
        sum1 += (m.z ? v[j].z : 0.0f) + (m.w ? v[j].w : 0.0f);
        icnt += (m.x != 0) + (m.y != 0) + (m.z != 0) + (m.w != 0);
        mx = fmaxf(mx, fmaxf(fmaxf(v[j].x, v[j].y), fmaxf(v[j].z, v[j].w)));
    }
    if (tail) {
        int4 m = mr[lane + 192];
        sum0 += (m.x ? v[6].x : 0.0f) + (m.y ? v[6].y : 0.0f);
        sum1 += (m.z ? v[6].z : 0.0f) + (m.w ? v[6].w : 0.0f);
        icnt += (m.x != 0) + (m.y != 0) + (m.z != 0) + (m.w != 0);
        mx = fmaxf(mx, fmaxf(fmaxf(v[6].x, v[6].y), fmaxf(v[6].z, v[6].w)));
    }

    // ---- 3. Warp reduce ----
    float sum = sum0 + sum1;
    #pragma unroll
    for (int off = 16; off > 0; off >>= 1) {
        sum  += __shfl_down_sync(0xffffffffu, sum, off);
        icnt += __shfl_down_sync(0xffffffffu, icnt, off);
        mx    = fmaxf(mx, __shfl_down_sync(0xffffffffu, mx, off));
    }

    if (lane == 0) {
        const int c = bc & (C_DIM - 1);
        sum += v[0].x;                       // + x[b,c,0,0] quirk: already in regs
        float fcnt  = (float)icnt;
        float denom = (icnt == 0) ? 1.0f : fcnt;
        out[(size_t)b * (2 * C_DIM) + c]         = sum / denom;
        out[(size_t)b * (2 * C_DIM) + C_DIM + c] = mx;
    }
}

extern "C" void kernel_launch(void* const* d_in, const int* in_sizes, int n_in,
                              void* d_out, int out_size)
{
    const float* x  = (const float*)d_in[0];
    const int*   cc = (const int*)d_in[1];
    float*       o  = (float*)d_out;

    // grid = 32768 rows / 4 rows per CTA = 8192
    pool_kernel<<<(64 * C_DIM) / ROWS_PER_CTA, THREADS>>>(x, cc, o);
}